// round 1
// baseline (speedup 1.0000x reference)
#include <cuda_runtime.h>

// Problem constants
#define B_  32
#define S_  256
#define D_  17
#define M_  512
#define H_  8
#define DK_ 64
#define NROW  (B_ * S_ * D_)   // 139264 rows of width 512
#define NSAMP (B_ * S_)        // 8192 samples

// Scratch (allocation-free rule: __device__ globals)
__device__ float g_q[(size_t)NROW * M_];
__device__ float g_k[(size_t)NROW * M_];
__device__ float g_v[(size_t)NROW * M_];
__device__ float g_ctx[(size_t)NROW * M_];

// ---------------------------------------------------------------------------
// GEMM (TN): C[r,c] = sum_m A[r,m] * W[c,m]
//   MODE 0: plain store
//   MODE 1: C[r,c] = acc + bias[c] + resid[r,c]   (fc_out + residual)
// 128x128 tile, BK=16, 256 threads, 8x8 per-thread microtile.
// ---------------------------------------------------------------------------
template<int MODE>
__global__ __launch_bounds__(256, 2)
void gemm_tn_128x128(const float* __restrict__ A, const float* __restrict__ W,
                     float* __restrict__ C, const float* __restrict__ bias,
                     const float* __restrict__ resid)
{
    __shared__ float As[16 * 132];   // [k][row], padded stride 132 (bank-safe)
    __shared__ float Bs[16 * 132];   // [k][col]

    const int tid = threadIdx.x;
    const int r0 = blockIdx.x * 128;
    const int c0 = blockIdx.y * 128;
    const int tx = tid & 15;         // 16 col-groups
    const int ty = tid >> 4;         // 16 row-groups

    float acc[8][8];
    #pragma unroll
    for (int i = 0; i < 8; i++)
        #pragma unroll
        for (int j = 0; j < 8; j++) acc[i][j] = 0.f;

    for (int kk = 0; kk < 512; kk += 16) {
        // Cooperative loads: 512 float4 per tile per matrix, fully coalesced
        #pragma unroll
        for (int u = 0; u < 2; u++) {
            int f   = tid + u * 256;   // 0..511
            int row = f >> 2;          // 0..127
            int c4  = f & 3;           // float4 slot within the 16-wide k-strip
            float4 va = *(const float4*)(A + (size_t)(r0 + row) * 512 + kk + c4 * 4);
            float4 vb = *(const float4*)(W + (size_t)(c0 + row) * 512 + kk + c4 * 4);
            int kb = c4 * 4;
            As[(kb + 0) * 132 + row] = va.x;
            As[(kb + 1) * 132 + row] = va.y;
            As[(kb + 2) * 132 + row] = va.z;
            As[(kb + 3) * 132 + row] = va.w;
            Bs[(kb + 0) * 132 + row] = vb.x;
            Bs[(kb + 1) * 132 + row] = vb.y;
            Bs[(kb + 2) * 132 + row] = vb.z;
            Bs[(kb + 3) * 132 + row] = vb.w;
        }
        __syncthreads();

        #pragma unroll
        for (int k = 0; k < 16; k++) {
            float a[8], b[8];
            *(float4*)(a)     = *(const float4*)&As[k * 132 + ty * 8];
            *(float4*)(a + 4) = *(const float4*)&As[k * 132 + ty * 8 + 4];
            *(float4*)(b)     = *(const float4*)&Bs[k * 132 + tx * 8];
            *(float4*)(b + 4) = *(const float4*)&Bs[k * 132 + tx * 8 + 4];
            #pragma unroll
            for (int i = 0; i < 8; i++)
                #pragma unroll
                for (int j = 0; j < 8; j++)
                    acc[i][j] = fmaf(a[i], b[j], acc[i][j]);
        }
        __syncthreads();
    }

    #pragma unroll
    for (int i = 0; i < 8; i++) {
        int r = r0 + ty * 8 + i;
        #pragma unroll
        for (int jj = 0; jj < 2; jj++) {
            int c = c0 + tx * 8 + jj * 4;
            float4 v;
            v.x = acc[i][jj * 4 + 0];
            v.y = acc[i][jj * 4 + 1];
            v.z = acc[i][jj * 4 + 2];
            v.w = acc[i][jj * 4 + 3];
            if (MODE == 1) {
                const float4 bb = *(const float4*)(bias + c);
                const float4 rr = *(const float4*)(resid + (size_t)r * 512 + c);
                v.x += bb.x + rr.x;
                v.y += bb.y + rr.y;
                v.z += bb.z + rr.z;
                v.w += bb.w + rr.w;
            }
            *(float4*)(C + (size_t)r * 512 + c) = v;
        }
    }
}

// ---------------------------------------------------------------------------
// Attention per sample n: for each head h
//   scores[d,e] = (q[d]·k[e]) / 8 + P[d,e];  attn = softmax_e;  ctx = attn @ v
// q/k/v layout: buf[(n*17+d)*512 + h*64 + kd]
// ---------------------------------------------------------------------------
__global__ __launch_bounds__(256)
void attn_kernel(const float* __restrict__ q, const float* __restrict__ k,
                 const float* __restrict__ v, const float* __restrict__ P,
                 float* __restrict__ ctx)
{
    __shared__ float sq[17 * 65];   // stride 65: bank-conflict-free e-strided reads
    __shared__ float sk[17 * 65];
    __shared__ float sv[17 * 65];
    __shared__ float sp[17 * 18];
    __shared__ float ss[17 * 18];

    const int n = blockIdx.x;
    const int t = threadIdx.x;
    const size_t base = (size_t)n * D_ * M_;

    for (int i = t; i < 289; i += 256)
        sp[(i / 17) * 18 + (i % 17)] = P[i];

    for (int h = 0; h < H_; h++) {
        __syncthreads();   // protect previous iteration's smem reads
        for (int i = t; i < D_ * DK_; i += 256) {
            int d = i >> 6, c = i & 63;
            size_t off = base + (size_t)d * M_ + h * DK_ + c;
            sq[d * 65 + c] = q[off];
            sk[d * 65 + c] = k[off];
            sv[d * 65 + c] = v[off];
        }
        __syncthreads();

        for (int s = t; s < 289; s += 256) {
            int d = s / 17, e = s % 17;
            float acc = 0.f;
            #pragma unroll
            for (int c = 0; c < DK_; c++)
                acc = fmaf(sq[d * 65 + c], sk[e * 65 + c], acc);
            ss[d * 18 + e] = acc * 0.125f + sp[d * 18 + e];
        }
        __syncthreads();

        if (t < 17) {
            float mx = -1e30f;
            #pragma unroll
            for (int e = 0; e < 17; e++) mx = fmaxf(mx, ss[t * 18 + e]);
            float sum = 0.f;
            #pragma unroll
            for (int e = 0; e < 17; e++) {
                float ex = __expf(ss[t * 18 + e] - mx);
                ss[t * 18 + e] = ex;
                sum += ex;
            }
            float inv = 1.f / sum;
            #pragma unroll
            for (int e = 0; e < 17; e++) ss[t * 18 + e] *= inv;
        }
        __syncthreads();

        for (int o = t; o < D_ * DK_; o += 256) {
            int d = o >> 6, c = o & 63;
            float acc = 0.f;
            #pragma unroll
            for (int e = 0; e < 17; e++)
                acc = fmaf(ss[d * 18 + e], sv[e * 65 + c], acc);
            ctx[base + (size_t)d * M_ + h * DK_ + c] = acc;
        }
    }
}

// ---------------------------------------------------------------------------
// In-place LayerNorm over last dim (512), warp per row. eps = 1e-5 (torch).
// ---------------------------------------------------------------------------
__global__ __launch_bounds__(256)
void ln_kernel(float* __restrict__ out, const float* __restrict__ gamma,
               const float* __restrict__ beta)
{
    const int row  = blockIdx.x * 8 + (threadIdx.x >> 5);
    const int lane = threadIdx.x & 31;
    const size_t base = (size_t)row * 512;

    float4 vals[4];
    float sum = 0.f, sq = 0.f;
    #pragma unroll
    for (int j = 0; j < 4; j++) {
        vals[j] = *(const float4*)(out + base + (size_t)(j * 32 + lane) * 4);
        sum += vals[j].x + vals[j].y + vals[j].z + vals[j].w;
        sq  += vals[j].x * vals[j].x + vals[j].y * vals[j].y
             + vals[j].z * vals[j].z + vals[j].w * vals[j].w;
    }
    #pragma unroll
    for (int o = 16; o > 0; o >>= 1) {
        sum += __shfl_xor_sync(0xffffffffu, sum, o);
        sq  += __shfl_xor_sync(0xffffffffu, sq,  o);
    }
    const float mean = sum * (1.f / 512.f);
    const float var  = sq * (1.f / 512.f) - mean * mean;
    const float rstd = rsqrtf(var + 1e-5f);

    #pragma unroll
    for (int j = 0; j < 4; j++) {
        int c = (j * 32 + lane) * 4;
        float4 g  = *(const float4*)(gamma + c);
        float4 bb = *(const float4*)(beta + c);
        float4 v;
        v.x = (vals[j].x - mean) * rstd * g.x + bb.x;
        v.y = (vals[j].y - mean) * rstd * g.y + bb.y;
        v.z = (vals[j].z - mean) * rstd * g.z + bb.z;
        v.w = (vals[j].w - mean) * rstd * g.w + bb.w;
        *(float4*)(out + base + c) = v;
    }
}

// ---------------------------------------------------------------------------
extern "C" void kernel_launch(void* const* d_in, const int* in_sizes, int n_in,
                              void* d_out, int out_size)
{
    const float* x     = (const float*)d_in[0];
    const float* P     = (const float*)d_in[1];
    const float* Wq    = (const float*)d_in[2];
    const float* Wk    = (const float*)d_in[3];
    const float* Wv    = (const float*)d_in[4];
    const float* Wo    = (const float*)d_in[5];
    const float* bo    = (const float*)d_in[6];
    const float* gamma = (const float*)d_in[7];
    const float* beta  = (const float*)d_in[8];
    float* out = (float*)d_out;

    void *pq, *pk, *pv, *pctx;
    cudaGetSymbolAddress(&pq,  g_q);
    cudaGetSymbolAddress(&pk,  g_k);
    cudaGetSymbolAddress(&pv,  g_v);
    cudaGetSymbolAddress(&pctx, g_ctx);

    dim3 gg(NROW / 128, M_ / 128);   // (1088, 4)

    gemm_tn_128x128<0><<<gg, 256>>>(x, Wq, (float*)pq, nullptr, nullptr);
    gemm_tn_128x128<0><<<gg, 256>>>(x, Wk, (float*)pk, nullptr, nullptr);
    gemm_tn_128x128<0><<<gg, 256>>>(x, Wv, (float*)pv, nullptr, nullptr);

    attn_kernel<<<NSAMP, 256>>>((const float*)pq, (const float*)pk,
                                (const float*)pv, P, (float*)pctx);

    gemm_tn_128x128<1><<<gg, 256>>>((const float*)pctx, Wo, out, bo, x);

    ln_kernel<<<NROW / 8, 256>>>(out, gamma, beta);
}

// round 3
// speedup vs baseline: 2.0243x; 2.0243x over previous
#include <cuda_runtime.h>
#include <cuda_bf16.h>
#include <cstdint>

// Problem constants
#define B_  32
#define S_  256
#define D_  17
#define M_  512
#define H_  8
#define DK_ 64
#define NROW  139264          // B*S*D rows of width 512
#define NSAMP 8192            // B*S

// ---------------------------------------------------------------------------
// Scratch (__device__ globals; allocation-free rule)
// ---------------------------------------------------------------------------
__device__ float g_q[(size_t)NROW * M_];
__device__ float g_k[(size_t)NROW * M_];
__device__ float g_v[(size_t)NROW * M_];
__device__ __nv_bfloat16 g_xh[(size_t)NROW * M_];
__device__ __nv_bfloat16 g_xl[(size_t)NROW * M_];
__device__ __nv_bfloat16 g_ch[(size_t)NROW * M_];
__device__ __nv_bfloat16 g_cl[(size_t)NROW * M_];
__device__ __nv_bfloat16 g_wh[4 * 512 * 512];
__device__ __nv_bfloat16 g_wl[4 * 512 * 512];

// ---------------------------------------------------------------------------
// Helpers
// ---------------------------------------------------------------------------
__device__ __forceinline__ uint32_t smem_u32(const void* p) {
    uint32_t a;
    asm("{ .reg .u64 t; cvta.to.shared.u64 t, %1; cvt.u32.u64 %0, t; }"
        : "=r"(a) : "l"(p));
    return a;
}

__device__ __forceinline__ void cp16(uint32_t dst, const void* src) {
    asm volatile("cp.async.cg.shared.global [%0], [%1], 16;" :: "r"(dst), "l"(src));
}

__device__ __forceinline__ void ldmx4(uint32_t* r, uint32_t addr) {
    asm volatile("ldmatrix.sync.aligned.m8n8.x4.shared.b16 {%0,%1,%2,%3}, [%4];"
                 : "=r"(r[0]), "=r"(r[1]), "=r"(r[2]), "=r"(r[3]) : "r"(addr));
}

__device__ __forceinline__ void mma16816(float* d, const uint32_t* a,
                                         uint32_t b0, uint32_t b1) {
    asm volatile(
        "mma.sync.aligned.m16n8k16.row.col.f32.bf16.bf16.f32 "
        "{%0,%1,%2,%3}, {%4,%5,%6,%7}, {%8,%9}, {%0,%1,%2,%3};"
        : "+f"(d[0]), "+f"(d[1]), "+f"(d[2]), "+f"(d[3])
        : "r"(a[0]), "r"(a[1]), "r"(a[2]), "r"(a[3]), "r"(b0), "r"(b1));
}

// ---------------------------------------------------------------------------
// bf16-split GEMM on HMMA (mma.sync):
//   C[r,c] = sum over virtual K=1536: phases hi.hi | hi.lo | lo.hi
//   BM=128, BN=128, BK=32, 8 warps (4m x 2n), warp tile 32x64.
//   smem rows padded to 40 elements (80B) -> conflict-free ldmatrix.
// ---------------------------------------------------------------------------
#define STAGES 3
#define KSTEPS 48
#define LDS_E 40                         // elements per padded row
#define STAGE_BYTES (256 * LDS_E * 2)    // A(128 rows) + B(128 rows)

__device__ __forceinline__ void load_tiles(
    int tid, uint32_t abase, uint32_t bbase, int r0, int c0, int kk,
    const __nv_bfloat16* __restrict__ A, const __nv_bfloat16* __restrict__ B)
{
    #pragma unroll
    for (int t = 0; t < 2; t++) {
        int f   = tid + t * 256;       // 0..511
        int row = f >> 2;              // 0..127
        int ch  = f & 3;               // 16B chunk in 64B row
        cp16(abase + row * 80 + ch * 16, A + ((size_t)(r0 + row) << 9) + kk + ch * 8);
        cp16(bbase + row * 80 + ch * 16, B + ((size_t)(c0 + row) << 9) + kk + ch * 8);
    }
    asm volatile("cp.async.commit_group;");
}

template<int MODE>
__global__ __launch_bounds__(256, 2)
void gemm_mma(const __nv_bfloat16* __restrict__ Ah,
              const __nv_bfloat16* __restrict__ Al,
              const __nv_bfloat16* __restrict__ Wh,
              const __nv_bfloat16* __restrict__ Wl,
              float* __restrict__ C,
              const float* __restrict__ bias,
              const float* __restrict__ resid)
{
    extern __shared__ __align__(128) char smem[];

    const int tid = threadIdx.x;
    const int wid = tid >> 5;
    const int lid = tid & 31;
    const int c0 = blockIdx.x << 7;
    const int r0 = blockIdx.y << 7;
    const int m0 = (wid & 3) * 32;     // warp m origin in tile
    const int n0 = (wid >> 2) * 64;    // warp n origin in tile
    const uint32_t sb = smem_u32(smem);

    float acc[2][8][4];
    #pragma unroll
    for (int i = 0; i < 2; i++)
        #pragma unroll
        for (int j = 0; j < 8; j++)
            #pragma unroll
            for (int q = 0; q < 4; q++) acc[i][j][q] = 0.f;

    // Prologue: k-steps 0,1 (phase 0: hi.hi)
    #pragma unroll
    for (int s = 0; s < STAGES - 1; s++)
        load_tiles(tid, sb + s * STAGE_BYTES, sb + s * STAGE_BYTES + 128 * 80,
                   r0, c0, s * 32, Ah, Wh);

    // ldmatrix address components (stage-invariant offsets)
    const uint32_t a_off = (uint32_t)((m0 + (lid & 15)) * 80 + ((lid >> 4) << 3) * 2);
    const uint32_t b_off = (uint32_t)((n0 + (lid & 7) + ((lid >> 4) << 3)) * 80
                                      + (((lid >> 3) & 1) << 3) * 2);

    for (int kc = 0; kc < KSTEPS; kc++) {
        const int s = kc % STAGES;
        if (kc < KSTEPS - 1) asm volatile("cp.async.wait_group 1;");
        else                 asm volatile("cp.async.wait_group 0;");
        __syncthreads();

        // Prefetch k-step kc+2 into the stage consumed at kc-1
        const int pf = kc + STAGES - 1;
        if (pf < KSTEPS) {
            const int ph = pf >> 4;
            const __nv_bfloat16* As = (ph < 2) ? Ah : Al;
            const __nv_bfloat16* Bs = (ph == 1) ? Wl : Wh;
            const int ps = pf % STAGES;
            load_tiles(tid, sb + ps * STAGE_BYTES, sb + ps * STAGE_BYTES + 128 * 80,
                       r0, c0, (pf & 15) << 5, As, Bs);
        }

        const uint32_t as = sb + s * STAGE_BYTES;
        const uint32_t bs = as + 128 * 80;

        #pragma unroll
        for (int kt = 0; kt < 2; kt++) {
            uint32_t a[2][4], b[4][4];
            #pragma unroll
            for (int mi = 0; mi < 2; mi++)
                ldmx4(a[mi], as + a_off + (uint32_t)(mi * 16 * 80 + kt * 32));
            #pragma unroll
            for (int nj = 0; nj < 4; nj++)
                ldmx4(b[nj], bs + b_off + (uint32_t)(nj * 16 * 80 + kt * 32));
            #pragma unroll
            for (int mi = 0; mi < 2; mi++)
                #pragma unroll
                for (int ni = 0; ni < 8; ni++)
                    mma16816(acc[mi][ni], a[mi],
                             b[ni >> 1][(ni & 1) * 2], b[ni >> 1][(ni & 1) * 2 + 1]);
        }
    }

    // Epilogue
    const int g  = lid >> 2;
    const int tg = lid & 3;
    #pragma unroll
    for (int mi = 0; mi < 2; mi++) {
        #pragma unroll
        for (int ni = 0; ni < 8; ni++) {
            const int r = r0 + m0 + mi * 16 + g;
            const int c = c0 + n0 + ni * 8 + tg * 2;
            float2 v0 = make_float2(acc[mi][ni][0], acc[mi][ni][1]);
            float2 v1 = make_float2(acc[mi][ni][2], acc[mi][ni][3]);
            if (MODE == 1) {
                const float2 bb = *(const float2*)(bias + c);
                const float2 q0 = *(const float2*)(resid + ((size_t)r << 9) + c);
                const float2 q1 = *(const float2*)(resid + ((size_t)(r + 8) << 9) + c);
                v0.x += bb.x + q0.x; v0.y += bb.y + q0.y;
                v1.x += bb.x + q1.x; v1.y += bb.y + q1.y;
            }
            *(float2*)(C + ((size_t)r << 9) + c)       = v0;
            *(float2*)(C + ((size_t)(r + 8) << 9) + c) = v1;
        }
    }
}

// ---------------------------------------------------------------------------
// fp32 -> (bf16 hi, bf16 lo) split
// ---------------------------------------------------------------------------
__global__ __launch_bounds__(256)
void split_kernel(const float* __restrict__ in, __nv_bfloat16* __restrict__ hi,
                  __nv_bfloat16* __restrict__ lo, int n4)
{
    int i = blockIdx.x * 256 + threadIdx.x;
    if (i >= n4) return;
    float4 v = ((const float4*)in)[i];
    __nv_bfloat16 h0 = __float2bfloat16(v.x);
    __nv_bfloat16 h1 = __float2bfloat16(v.y);
    __nv_bfloat16 h2 = __float2bfloat16(v.z);
    __nv_bfloat16 h3 = __float2bfloat16(v.w);
    __nv_bfloat162* hp = (__nv_bfloat162*)hi;
    __nv_bfloat162* lp = (__nv_bfloat162*)lo;
    hp[2 * i]     = __nv_bfloat162(h0, h1);
    hp[2 * i + 1] = __nv_bfloat162(h2, h3);
    lp[2 * i]     = __nv_bfloat162(__float2bfloat16(v.x - __bfloat162float(h0)),
                                   __float2bfloat16(v.y - __bfloat162float(h1)));
    lp[2 * i + 1] = __nv_bfloat162(__float2bfloat16(v.z - __bfloat162float(h2)),
                                   __float2bfloat16(v.w - __bfloat162float(h3)));
}

// ---------------------------------------------------------------------------
// Attention per sample; epilogue emits ctx as bf16 hi/lo (feeds fc GEMM)
// ---------------------------------------------------------------------------
__global__ __launch_bounds__(256)
void attn_kernel(const float* __restrict__ q, const float* __restrict__ k,
                 const float* __restrict__ v, const float* __restrict__ P,
                 __nv_bfloat16* __restrict__ ch, __nv_bfloat16* __restrict__ cl)
{
    __shared__ float sq[17 * 65];
    __shared__ float sk[17 * 65];
    __shared__ float sv[17 * 65];
    __shared__ float sp[17 * 18];
    __shared__ float ss[17 * 18];

    const int n = blockIdx.x;
    const int t = threadIdx.x;
    const size_t base = (size_t)n * D_ * M_;

    for (int i = t; i < 289; i += 256)
        sp[(i / 17) * 18 + (i % 17)] = P[i];

    for (int h = 0; h < H_; h++) {
        __syncthreads();
        for (int i = t; i < D_ * DK_; i += 256) {
            int d = i >> 6, c = i & 63;
            size_t off = base + (size_t)d * M_ + h * DK_ + c;
            sq[d * 65 + c] = q[off];
            sk[d * 65 + c] = k[off];
            sv[d * 65 + c] = v[off];
        }
        __syncthreads();

        for (int s = t; s < 289; s += 256) {
            int d = s / 17, e = s % 17;
            float acc = 0.f;
            #pragma unroll
            for (int c = 0; c < DK_; c++)
                acc = fmaf(sq[d * 65 + c], sk[e * 65 + c], acc);
            ss[d * 18 + e] = acc * 0.125f + sp[d * 18 + e];
        }
        __syncthreads();

        if (t < 17) {
            float mx = -1e30f;
            #pragma unroll
            for (int e = 0; e < 17; e++) mx = fmaxf(mx, ss[t * 18 + e]);
            float sum = 0.f;
            #pragma unroll
            for (int e = 0; e < 17; e++) {
                float ex = __expf(ss[t * 18 + e] - mx);
                ss[t * 18 + e] = ex;
                sum += ex;
            }
            float inv = 1.f / sum;
            #pragma unroll
            for (int e = 0; e < 17; e++) ss[t * 18 + e] *= inv;
        }
        __syncthreads();

        for (int o = t; o < D_ * DK_; o += 256) {
            int d = o >> 6, c = o & 63;
            float acc = 0.f;
            #pragma unroll
            for (int e = 0; e < 17; e++)
                acc = fmaf(ss[d * 18 + e], sv[e * 65 + c], acc);
            size_t off = base + (size_t)d * M_ + h * DK_ + c;
            __nv_bfloat16 hh = __float2bfloat16(acc);
            ch[off] = hh;
            cl[off] = __float2bfloat16(acc - __bfloat162float(hh));
        }
    }
}

// ---------------------------------------------------------------------------
// In-place LayerNorm (warp per row, width 512), eps = 1e-5
// ---------------------------------------------------------------------------
__global__ __launch_bounds__(256)
void ln_kernel(float* __restrict__ out, const float* __restrict__ gamma,
               const float* __restrict__ beta)
{
    const int row  = blockIdx.x * 8 + (threadIdx.x >> 5);
    const int lane = threadIdx.x & 31;
    const size_t base = (size_t)row * 512;

    float4 vals[4];
    float sum = 0.f, sq = 0.f;
    #pragma unroll
    for (int j = 0; j < 4; j++) {
        vals[j] = *(const float4*)(out + base + (size_t)(j * 32 + lane) * 4);
        sum += vals[j].x + vals[j].y + vals[j].z + vals[j].w;
        sq  += vals[j].x * vals[j].x + vals[j].y * vals[j].y
             + vals[j].z * vals[j].z + vals[j].w * vals[j].w;
    }
    #pragma unroll
    for (int o = 16; o > 0; o >>= 1) {
        sum += __shfl_xor_sync(0xffffffffu, sum, o);
        sq  += __shfl_xor_sync(0xffffffffu, sq,  o);
    }
    const float mean = sum * (1.f / 512.f);
    const float var  = sq * (1.f / 512.f) - mean * mean;
    const float rstd = rsqrtf(var + 1e-5f);

    #pragma unroll
    for (int j = 0; j < 4; j++) {
        int c = (j * 32 + lane) * 4;
        float4 g  = *(const float4*)(gamma + c);
        float4 bb = *(const float4*)(beta + c);
        float4 v;
        v.x = (vals[j].x - mean) * rstd * g.x + bb.x;
        v.y = (vals[j].y - mean) * rstd * g.y + bb.y;
        v.z = (vals[j].z - mean) * rstd * g.z + bb.z;
        v.w = (vals[j].w - mean) * rstd * g.w + bb.w;
        *(float4*)(out + base + c) = v;
    }
}

// ---------------------------------------------------------------------------
extern "C" void kernel_launch(void* const* d_in, const int* in_sizes, int n_in,
                              void* d_out, int out_size)
{
    const float* x     = (const float*)d_in[0];
    const float* P     = (const float*)d_in[1];
    const float* Wq    = (const float*)d_in[2];
    const float* Wk    = (const float*)d_in[3];
    const float* Wv    = (const float*)d_in[4];
    const float* Wo    = (const float*)d_in[5];
    const float* bo    = (const float*)d_in[6];
    const float* gamma = (const float*)d_in[7];
    const float* beta  = (const float*)d_in[8];
    float* out = (float*)d_out;

    void *pq, *pk, *pv, *pxh, *pxl, *pch, *pcl, *pwh, *pwl;
    cudaGetSymbolAddress(&pq,  g_q);
    cudaGetSymbolAddress(&pk,  g_k);
    cudaGetSymbolAddress(&pv,  g_v);
    cudaGetSymbolAddress(&pxh, g_xh);
    cudaGetSymbolAddress(&pxl, g_xl);
    cudaGetSymbolAddress(&pch, g_ch);
    cudaGetSymbolAddress(&pcl, g_cl);
    cudaGetSymbolAddress(&pwh, g_wh);
    cudaGetSymbolAddress(&pwl, g_wl);

    __nv_bfloat16* wh = (__nv_bfloat16*)pwh;
    __nv_bfloat16* wl = (__nv_bfloat16*)pwl;

    const int dsm = STAGES * STAGE_BYTES;   // 61440
    cudaFuncSetAttribute(gemm_mma<0>, cudaFuncAttributeMaxDynamicSharedMemorySize, dsm);
    cudaFuncSetAttribute(gemm_mma<1>, cudaFuncAttributeMaxDynamicSharedMemorySize, dsm);

    // Splits
    const int nw4 = 512 * 512 / 4;
    split_kernel<<<(nw4 + 255) / 256, 256>>>(Wq, wh + 0 * 262144, wl + 0 * 262144, nw4);
    split_kernel<<<(nw4 + 255) / 256, 256>>>(Wk, wh + 1 * 262144, wl + 1 * 262144, nw4);
    split_kernel<<<(nw4 + 255) / 256, 256>>>(Wv, wh + 2 * 262144, wl + 2 * 262144, nw4);
    split_kernel<<<(nw4 + 255) / 256, 256>>>(Wo, wh + 3 * 262144, wl + 3 * 262144, nw4);
    const int nx4 = (int)((size_t)NROW * 512 / 4);
    split_kernel<<<(nx4 + 255) / 256, 256>>>(x, (__nv_bfloat16*)pxh,
                                             (__nv_bfloat16*)pxl, nx4);

    // Projections on HMMA
    dim3 gg(4, NROW / 128);   // (4, 1088)
    gemm_mma<0><<<gg, 256, dsm>>>((const __nv_bfloat16*)pxh, (const __nv_bfloat16*)pxl,
                                  wh + 0 * 262144, wl + 0 * 262144,
                                  (float*)pq, nullptr, nullptr);
    gemm_mma<0><<<gg, 256, dsm>>>((const __nv_bfloat16*)pxh, (const __nv_bfloat16*)pxl,
                                  wh + 1 * 262144, wl + 1 * 262144,
                                  (float*)pk, nullptr, nullptr);
    gemm_mma<0><<<gg, 256, dsm>>>((const __nv_bfloat16*)pxh, (const __nv_bfloat16*)pxl,
                                  wh + 2 * 262144, wl + 2 * 262144,
                                  (float*)pv, nullptr, nullptr);

    attn_kernel<<<NSAMP, 256>>>((const float*)pq, (const float*)pk,
                                (const float*)pv, P,
                                (__nv_bfloat16*)pch, (__nv_bfloat16*)pcl);

    gemm_mma<1><<<gg, 256, dsm>>>((const __nv_bfloat16*)pch, (const __nv_bfloat16*)pcl,
                                  wh + 3 * 262144, wl + 3 * 262144,
                                  out, bo, x);

    ln_kernel<<<NROW / 8, 256>>>(out, gamma, beta);
}